// round 17
// baseline (speedup 1.0000x reference)
#include <cuda_runtime.h>
#include <cuda_fp16.h>
#include <cstdint>
#include <cstring>

// Problem dims (fixed by setup_inputs)
constexpr int Bd = 4;
constexpr int Sd = 2048;
constexpr int Ed = 1024;
constexpr float SCALE_F = 0.125f;
constexpr int KS = 32;       // split-K factor for mv2 jobs
constexpr int KSW = 32;      // row-tile partials from tsplitW (Ed/32)
constexpr int CS = Sd / 32;  // 64 colsum tile-partials per batch

// ===========================================================================
// scratch layout (bytes) — fp16 hi-limb arrays only (1-product engine)
// ===========================================================================
constexpr long MB = 1024 * 1024;
constexpr long OFF_XS_H = 0;          // x hi   [B][S][E]  16MB
constexpr long OFF_XT_H = 32 * MB;    // x^T hi [B][E][S]  16MB
constexpr long OFF_WQT_H = 64 * MB;   // Wq^T hi [E][E]     2MB
constexpr long OFF_WKT_H = 68 * MB;
constexpr long OFF_WVT_H = 72 * MB;
constexpr long OFF_WO_H  = 76 * MB;   // Wo hi (no transpose)
constexpr long OFF_P_H   = 80 * MB;   // P = Wq^T Wk
constexpr long OFF_Q_H   = 84 * MB;   // Q = Wo Wv
constexpr long OFF_G_H   = 88 * MB;   // G  [B][E][E]  8MB
constexpr long OFF_R_H   = 104 * MB;  // R = Q G
constexpr long OFF_UT_H  = 120 * MB;  // U^T
constexpr long OFF_VEC   = 130 * MB;  // fp32 vectors + partials
constexpr long SCRATCH_BYTES = 136 * MB;

__device__ __align__(1024) char g_scratch[SCRATCH_BYTES];

// ===========================================================================
// helpers
// ===========================================================================
__device__ __forceinline__ uint32_t smem_u32(const void* p) {
    uint32_t a;
    asm("{ .reg .u64 t; cvta.to.shared.u64 t, %1; cvt.u32.u64 %0, t; }" : "=r"(a) : "l"(p));
    return a;
}
#define SWZ128(o) ((o) ^ (((o) >> 3) & 0x70))

__device__ __forceinline__ uint32_t pack2(float a, float b) {
    __half ha = __float2half_rn(a), hb = __float2half_rn(b);
    uint16_t ua, ub;
    memcpy(&ua, &ha, 2); memcpy(&ub, &hb, 2);
    return (uint32_t)ua | ((uint32_t)ub << 16);
}

#define LDMX4(r0, r1, r2, r3, addr)                                            \
    asm volatile("ldmatrix.sync.aligned.m8n8.x4.shared.b16 {%0,%1,%2,%3}, [%4];" \
                 : "=r"(r0), "=r"(r1), "=r"(r2), "=r"(r3) : "r"(addr))

__device__ __forceinline__ void mma16816(float* c, const uint32_t* a, const uint32_t* b) {
    asm volatile(
        "mma.sync.aligned.m16n8k16.row.col.f32.f16.f16.f32 "
        "{%0,%1,%2,%3},{%4,%5,%6,%7},{%8,%9},{%0,%1,%2,%3};"
        : "+f"(c[0]), "+f"(c[1]), "+f"(c[2]), "+f"(c[3])
        : "r"(a[0]), "r"(a[1]), "r"(a[2]), "r"(a[3]), "r"(b[0]), "r"(b[1]));
}
__device__ __forceinline__ void cp16(uint32_t dst, const void* src) {
    asm volatile("cp.async.cg.shared.global [%0], [%1], 16;" :: "r"(dst), "l"(src));
}

// ===========================================================================
// preprocessing
// ===========================================================================
// fused x preprocessing (x read exactly once):
//   xs_h[r][c] = hi(x[r][c]) ; xt_h[c][r] ; colsum tile-partials part_cs
__global__ void xsplit_k(const float* __restrict__ x, long sIn,
                         __half* __restrict__ xs_h, long sXs,
                         __half* __restrict__ xt_h, long sXt,
                         float* __restrict__ part_cs) {
    __shared__ float t[32][33];
    __shared__ float red[8][33];
    int b = blockIdx.z;
    x    += (long)b * sIn;
    xs_h += (long)b * sXs;
    xt_h += (long)b * sXt;
    int c0 = blockIdx.x * 32, r0 = blockIdx.y * 32;
    int tx = threadIdx.x, ty = threadIdx.y;  // (32,8)
    float cs = 0.f;
#pragma unroll
    for (int i = 0; i < 4; i++) {
        int rr = r0 + ty + i * 8;
        float v = x[(long)rr * Ed + c0 + tx];
        t[ty + i * 8][tx] = v;
        cs += v;
        xs_h[(long)rr * Ed + c0 + tx] = __float2half_rn(v);
    }
    red[ty][tx] = cs;
    __syncthreads();
#pragma unroll
    for (int i = 0; i < 4; i++) {
        float v = t[tx][ty + i * 8];
        xt_h[(long)(c0 + ty + i * 8) * Sd + r0 + tx] = __float2half_rn(v);
    }
    if (ty == 0) {
        float v = 0.f;
#pragma unroll
        for (int k = 0; k < 8; k++) v += red[k][tx];
        part_cs[((long)b * CS + blockIdx.y) * Ed + c0 + tx] = v;
    }
}

// z=0: Wq^T (+ u2 partials vs bk) ; z=1: Wk^T (+ t1 partials vs bq) ;
// z=2: Wv^T ; z=3: Wo hi straight copy.
__global__ void tsplitW_k(const float* __restrict__ Wq, const float* __restrict__ Wk,
                          const float* __restrict__ Wv, const float* __restrict__ Wo,
                          const float* __restrict__ bk, const float* __restrict__ bq,
                          __half* __restrict__ wqt_h,
                          __half* __restrict__ wkt_h, __half* __restrict__ wvt_h,
                          __half* __restrict__ wo_h,
                          float* __restrict__ part_w) {
    int z = blockIdx.z;
    int c0 = blockIdx.x * 32, r0 = blockIdx.y * 32;
    int tx = threadIdx.x, ty = threadIdx.y;
    if (z == 3) {  // straight hi copy of Wo
#pragma unroll
        for (int i = 0; i < 4; i++) {
            int rr = r0 + ty + i * 8;
            wo_h[(long)rr * Ed + c0 + tx] =
                __float2half_rn(Wo[(long)rr * Ed + c0 + tx]);
        }
        return;
    }
    const float* in; __half* oh; const float* w;
    if (z == 0)      { in = Wq; oh = wqt_h; w = bk; }
    else if (z == 1) { in = Wk; oh = wkt_h; w = bq; }
    else             { in = Wv; oh = wvt_h; w = nullptr; }
    __shared__ float t[32][33];
    __shared__ float red[8][33];
    float pw = 0.f;
#pragma unroll
    for (int i = 0; i < 4; i++) {
        int rr = r0 + ty + i * 8;
        float v = in[(long)rr * Ed + c0 + tx];
        t[ty + i * 8][tx] = v;
        if (w) pw += v * w[rr];
    }
    if (w) red[ty][tx] = pw;
    __syncthreads();
#pragma unroll
    for (int i = 0; i < 4; i++)
        oh[(long)(c0 + ty + i * 8) * Ed + r0 + tx] =
            __float2half_rn(t[tx][ty + i * 8]);
    if (w && ty == 0) {
        float v = 0.f;
#pragma unroll
        for (int k = 0; k < 8; k++) v += red[k][tx];
        part_w[((long)z * KSW + blockIdx.y) * Ed + c0 + tx] = v;
    }
}

// mirror upper-triangle tiles of symmetric fp16 matrix into lower triangle
__global__ void mirror_k(__half* __restrict__ Gh, long sEE) {
    int bi = blockIdx.y, bj = blockIdx.x;
    if (bi > bj) return;
    __half* G = Gh + (long)blockIdx.z * sEE;
    __shared__ uint16_t t[32][33];
    int tx = threadIdx.x, ty = threadIdx.y;
    int r0 = bi * 32, c0 = bj * 32;
#pragma unroll
    for (int i = 0; i < 4; i++) {
        int r = ty + i * 8;
        uint16_t v;
        memcpy(&v, &G[(long)(r0 + r) * Ed + c0 + tx], 2);
        t[r][tx] = v;
    }
    __syncthreads();
#pragma unroll
    for (int i = 0; i < 4; i++) {
        int rr = ty + i * 8;
        int cc = tx;
        int dr = c0 + rr, dc = r0 + cc;
        if (dr > dc) {
            uint16_t v = t[cc][rr];
            memcpy(&G[(long)dr * Ed + dc], &v, 2);
        }
    }
}

// ===========================================================================
// vector kernels
// ===========================================================================
// Wide reduce: z=0: u2 ; z=1: t1 (KSW partials) ; z=2..5: s_b (CS partials)
// block = 64 j-cols x 4 k-slices, grid (Ed/64, 6)
__global__ void red1_k(const float* __restrict__ part_w, const float* __restrict__ part_cs,
                       float* __restrict__ u2, float* __restrict__ t1,
                       float* __restrict__ s) {
    __shared__ float red[4][64];
    int z = blockIdx.y;
    int jl = threadIdx.x & 63;
    int sl = threadIdx.x >> 6;       // 0..3
    int j = blockIdx.x * 64 + jl;
    const float* src;
    int nk;
    if (z < 2) { src = part_w + (long)z * KSW * Ed; nk = KSW; }
    else       { src = part_cs + (long)(z - 2) * CS * Ed; nk = CS; }
    int per = nk / 4;
    float a = 0.f;
    for (int k = sl * per; k < (sl + 1) * per; k++) a += src[(long)k * Ed + j];
    red[sl][jl] = a;
    __syncthreads();
    if (sl == 0) {
        float v = red[0][jl] + red[1][jl] + red[2][jl] + red[3][jl];
        float* y = (z == 0) ? u2 : (z == 1) ? t1 : s + (long)(z - 2) * Ed;
        y[j] = v;
    }
}

// z=0: p_b = Wk s_b ; z=1: r_b = Wv s_b ; z=2 (b==0): w1 = Wo bv ;
// z=3: y_b = x_b t1   (rows=Sd)
__global__ void rowdot_prw_k(const float* __restrict__ Wk, const float* __restrict__ Wv,
                             const float* __restrict__ Wo, const float* __restrict__ x, long sX,
                             const float* __restrict__ s, const float* __restrict__ bv,
                             const float* __restrict__ t1,
                             float* __restrict__ p, float* __restrict__ r,
                             float* __restrict__ w1, float* __restrict__ yv) {
    int z = blockIdx.z, b = blockIdx.y;
    const float* A; const float* xv; float* y; int rows;
    if (z == 0)      { A = Wk; xv = s + (long)b * Ed; y = p + (long)b * Ed; rows = Ed; }
    else if (z == 1) { A = Wv; xv = s + (long)b * Ed; y = r + (long)b * Ed; rows = Ed; }
    else if (z == 2) { if (b) return; A = Wo; xv = bv; y = w1; rows = Ed; }
    else             { A = x + (long)b * sX; xv = t1; y = yv + (long)b * Sd; rows = Sd; }
    int warp = blockIdx.x * 8 + (threadIdx.x >> 5);
    if (warp >= rows) return;
    int lane = threadIdx.x & 31;
    const float* row = A + (long)warp * Ed;
    float acc = 0.f;
    for (int j = lane; j < Ed; j += 32) acc += row[j] * xv[j];
#pragma unroll
    for (int o = 16; o > 0; o >>= 1) acc += __shfl_xor_sync(0xffffffffu, acc, o);
    if (lane == 0) y[warp] = acc;
}

// split-K partials: z<Bd: u1_b = Wq^T p_b ; z>=Bd: t2_b = x_b^T y_b
__global__ void mv2_part_k(const float* __restrict__ Wq, const float* __restrict__ p,
                           const float* __restrict__ x, long sX,
                           const float* __restrict__ yv,
                           float* __restrict__ part) {
    int z = blockIdx.z;
    const float* A; const float* w; int rows;
    if (z < Bd) { A = Wq; w = p + (long)z * Ed; rows = Ed; }
    else        { A = x + (long)(z - Bd) * sX; w = yv + (long)(z - Bd) * Sd; rows = Sd; }
    int j = blockIdx.x * 256 + threadIdx.x;
    int chunk = rows / KS;
    int r0 = blockIdx.y * chunk;
    float a0 = 0.f, a1 = 0.f;
    for (int i = 0; i < chunk; i += 2) {
        a0 += A[(long)(r0 + i) * Ed + j] * w[r0 + i];
        a1 += A[(long)(r0 + i + 1) * Ed + j] * w[r0 + i + 1];
    }
    part[((long)z * KS + blockIdx.y) * Ed + j] = a0 + a1;
}

// z=0: u1 reduce ; z=1: w2_b = Wo r_b ; z=2 (b==0): dp/db ; z=3: t2 reduce
__global__ void red2_k(const float* __restrict__ part,
                       const float* __restrict__ Wo, const float* __restrict__ r,
                       const float* __restrict__ p, const float* __restrict__ bk,
                       const float* __restrict__ bq,
                       float* __restrict__ u1, float* __restrict__ w2,
                       float* __restrict__ dp, float* __restrict__ db,
                       float* __restrict__ t2) {
    int z = blockIdx.z, b = blockIdx.y;
    if (z == 0 || z == 3) {
        if (blockIdx.x >= Ed / 256) return;
        int j = blockIdx.x * 256 + threadIdx.x;
        int zp = (z == 0) ? b : Bd + b;
        float a = 0.f;
#pragma unroll
        for (int ks = 0; ks < KS; ks++) a += part[((long)zp * KS + ks) * Ed + j];
        ((z == 0) ? u1 : t2)[(long)b * Ed + j] = a;
    } else if (z == 1) {
        int warp = blockIdx.x * 8 + (threadIdx.x >> 5);
        int lane = threadIdx.x & 31;
        const float* xv = r + (long)b * Ed;
        const float* row = Wo + (long)warp * Ed;
        float acc = 0.f;
        for (int j = lane; j < Ed; j += 32) acc += row[j] * xv[j];
#pragma unroll
        for (int o = 16; o > 0; o >>= 1) acc += __shfl_xor_sync(0xffffffffu, acc, o);
        if (lane == 0) w2[(long)b * Ed + warp] = acc;
    } else {
        if (b != 0) return;
        int bid = blockIdx.x;
        if (bid > Bd) return;
        const float* a = (bid < Bd) ? p + (long)bid * Ed : bk;
        __shared__ float red[8];
        int tid = threadIdx.x;
        float acc = 0.f;
        for (int j = tid; j < Ed; j += 256) acc += a[j] * bq[j];
#pragma unroll
        for (int o = 16; o > 0; o >>= 1) acc += __shfl_xor_sync(0xffffffffu, acc, o);
        if ((tid & 31) == 0) red[tid >> 5] = acc;
        __syncthreads();
        if (tid < 8) {
            float v = red[tid];
#pragma unroll
            for (int o = 4; o > 0; o >>= 1) v += __shfl_xor_sync(0xffu, v, o);
            if (tid == 0) { if (bid < Bd) dp[bid] = v; else db[0] = v; }
        }
    }
}

// cb_b[i] = SCALE*( dot(Q_h[i,:], t2_b) + w1[i]*(dp[b]+S*db) + w2_b[i]*db ) + bo[i]
__global__ void qcb_k(const __half* __restrict__ Qh,
                      const float* __restrict__ t2,
                      const float* __restrict__ w1, const float* __restrict__ w2,
                      const float* __restrict__ dp, const float* __restrict__ db,
                      const float* __restrict__ bo, float* __restrict__ cb) {
    int b = blockIdx.y;
    int warp = blockIdx.x * 8 + (threadIdx.x >> 5);
    int lane = threadIdx.x & 31;
    const __half* row = Qh + (long)warp * Ed;
    const float* xv = t2 + (long)b * Ed;
    float acc = 0.f;
    for (int j = lane; j < Ed; j += 32) acc += __half2float(row[j]) * xv[j];
#pragma unroll
    for (int o = 16; o > 0; o >>= 1) acc += __shfl_xor_sync(0xffffffffu, acc, o);
    if (lane == 0) {
        float dbv = db[0];
        cb[(long)b * Ed + warp] = SCALE_F * (acc + w1[warp] * (dp[b] + (float)Sd * dbv)
                                             + w2[(long)b * Ed + warp] * dbv) + bo[warp];
    }
}

// ===========================================================================
// fp16 1-product GEMM engine: C = alpha * A_hi B_hi^T [+ epilogue]
//   fuse mode: z<4 -> batched tri job (Kd) ; z=4 -> job2 (Kd2) ; z=5 -> job3 (Kd2)
// ===========================================================================
constexpr int OFF_A = 0;
constexpr int OFF_B = 16384;
constexpr int STAGE = 32768;
constexpr int DYN_SMEM = 4 * STAGE;  // 128 KB

__device__ __forceinline__ void issue_tile(uint32_t sdst, const __half* g,
                                           long ldK, int tid) {
#pragma unroll
    for (int i = 0; i < 2; i++) {
        int gi = tid + i * 512;
        int row = gi >> 3, c16 = gi & 7;
        uint32_t off = SWZ128((uint32_t)(row * 128 + c16 * 16));
        cp16(sdst + off, (const char*)(g + (long)row * ldK) + c16 * 16);
    }
}

__device__ __forceinline__ void compute_ks(uint32_t sb, int ks, int mw, int nw,
                                           int lane, float (&acc)[2][4][4]) {
    const uint32_t rowsel = lane & 15;
    const uint32_t ksel = (lane >> 4) * 16;
    uint32_t ah[2][4];
#pragma unroll
    for (int mt = 0; mt < 2; mt++) {
        uint32_t off = SWZ128((uint32_t)((mw + mt * 16 + rowsel) * 128 + ks * 32 + ksel));
        LDMX4(ah[mt][0], ah[mt][1], ah[mt][2], ah[mt][3], sb + OFF_A + off);
    }
    uint32_t bh[4][2];
#pragma unroll
    for (int nt = 0; nt < 2; nt++) {
        uint32_t off = SWZ128((uint32_t)((nw + nt * 16 + rowsel) * 128 + ks * 32 + ksel));
        uint32_t r0, r1, r2, r3;
        LDMX4(r0, r1, r2, r3, sb + OFF_B + off);
        bh[2 * nt][0] = r0; bh[2 * nt][1] = r2;
        bh[2 * nt + 1][0] = r1; bh[2 * nt + 1][1] = r3;
    }
#pragma unroll
    for (int mt = 0; mt < 2; mt++)
#pragma unroll
        for (int nf = 0; nf < 4; nf++)
            mma16816(acc[mt][nf], ah[mt], bh[nf]);
}

__global__ void __launch_bounds__(512, 1) hf_gemm(
    const __half* __restrict__ Ah, long sA,
    const __half* __restrict__ Bh, long sB,
    float* __restrict__ Cf, long sCf,
    __half* __restrict__ Ch, long sCb,
    int Nd, int Kd, float alpha, int mode, int tri, int fuse,
    const __half* __restrict__ A2h, const __half* __restrict__ B2h, __half* __restrict__ C2h,
    const __half* __restrict__ A3h, const __half* __restrict__ B3h, __half* __restrict__ C3h,
    int Kd2,
    const float* __restrict__ v1, int sv1, const float* __restrict__ v2,
    const float* __restrict__ v3, const float* __restrict__ v4, int sv4, float rk)
{
    extern __shared__ char smem[];
    const int bz = blockIdx.z;
    int KdL = Kd;
    int triL = tri;
    if (fuse) {
        if (bz == 4)      { Ah = A2h; Bh = B2h; Ch = C2h; KdL = Kd2; triL = 0; }
        else if (bz == 5) { Ah = A3h; Bh = B3h; Ch = C3h; KdL = Kd2; triL = 0; }
        else {
            Ah += (long)bz * sA;
            Bh += (long)bz * sB;
            Ch += (long)bz * sCb;
        }
    } else {
        Ah += (long)bz * sA;
        Bh += (long)bz * sB;
        if (Cf) Cf += (long)bz * sCf;
        if (Ch) Ch += (long)bz * sCb;
        if (v1) v1 += (long)bz * sv1;
        if (v4) v4 += (long)bz * sv4;
    }

    int m0, n0;
    if (triL) {
        if (blockIdx.x >= 36) return;
        int t = blockIdx.x, ti = 0;
        while (t >= 8 - ti) { t -= 8 - ti; ti++; }
        m0 = ti * 128;
        n0 = (ti + t) * 128;
    } else if (fuse) {
        m0 = (blockIdx.x >> 3) * 128;
        n0 = (blockIdx.x & 7) * 128;
    } else {
        m0 = blockIdx.y * 128;
        n0 = blockIdx.x * 128;
    }
    const int tid = threadIdx.x;
    const int lane = tid & 31;
    const int wid = tid >> 5;
    const int mw = (wid >> 2) * 32;
    const int nw = (wid & 3) * 32;
    const uint32_t sbase = smem_u32(smem);

    float acc[2][4][4];
#pragma unroll
    for (int mt = 0; mt < 2; mt++)
#pragma unroll
        for (int nf = 0; nf < 4; nf++)
#pragma unroll
            for (int q = 0; q < 4; q++) acc[mt][nf][q] = 0.f;

    const int nCh = KdL / 64;
    auto issue = [&](int c) {
        uint32_t sb = sbase + (uint32_t)(c & 3) * STAGE;
        long k0 = (long)c * 64;
        issue_tile(sb + OFF_A, Ah + (long)m0 * KdL + k0, KdL, tid);
        issue_tile(sb + OFF_B, Bh + (long)n0 * KdL + k0, KdL, tid);
        asm volatile("cp.async.commit_group;" ::: "memory");
    };

    issue(0); issue(1); issue(2);
    for (int c = 0; c < nCh; c++) {
        if (c + 3 <= nCh) {
            asm volatile("cp.async.wait_group 2;" ::: "memory");
        } else if (c + 2 == nCh) {
            asm volatile("cp.async.wait_group 1;" ::: "memory");
        } else {
            asm volatile("cp.async.wait_group 0;" ::: "memory");
        }
        __syncthreads();
        if (c + 3 < nCh) issue(c + 3);
        const uint32_t sb = sbase + (uint32_t)(c & 3) * STAGE;
        compute_ks(sb, 0, mw, nw, lane, acc);
        compute_ks(sb, 1, mw, nw, lane, acc);
        compute_ks(sb, 2, mw, nw, lane, acc);
        compute_ks(sb, 3, mw, nw, lane, acc);
    }
    __syncthreads();

    // epilogue
    const int r = lane >> 2;
    const int cp = (lane & 3) * 2;
#pragma unroll
    for (int mt = 0; mt < 2; mt++)
#pragma unroll
        for (int rr = 0; rr < 2; rr++) {
            const int m = m0 + mw + mt * 16 + r + rr * 8;
            float pv = 0.f, bkv = 0.f;
            if (mode == 1) { pv = v1[m]; bkv = v3[m]; }
#pragma unroll
            for (int nf = 0; nf < 4; nf++) {
                const int nloc = nf * 8 + cp;
                const int n = n0 + nw + nloc;
                float f0 = alpha * acc[mt][nf][rr * 2 + 0];
                float f1 = alpha * acc[mt][nf][rr * 2 + 1];
                if (mode == 1) {
                    f0 += pv * v2[n + 0] + bkv * (v4[n + 0] + rk * v2[n + 0]);
                    f1 += pv * v2[n + 1] + bkv * (v4[n + 1] + rk * v2[n + 1]);
                } else if (mode == 2) {
                    f0 += v1[n + 0];
                    f1 += v1[n + 1];
                }
                long co = (long)m * Nd + n;
                if (Cf) *(float2*)(Cf + co) = make_float2(f0, f1);
                if (Ch) *(uint32_t*)(Ch + co) = pack2(f0, f1);
            }
        }
}

// ===========================================================================
// Launch — single stream, 12 launches; GEMM phase uninterrupted.
// ===========================================================================
extern "C" void kernel_launch(void* const* d_in, const int* in_sizes, int n_in,
                              void* d_out, int out_size)
{
    const float* x  = (const float*)d_in[0];
    const float* Wq = (const float*)d_in[1];
    const float* bq = (const float*)d_in[2];
    const float* Wk = (const float*)d_in[3];
    const float* bk = (const float*)d_in[4];
    const float* Wv = (const float*)d_in[5];
    const float* bv = (const float*)d_in[6];
    const float* Wo = (const float*)d_in[7];
    const float* bo = (const float*)d_in[8];
    float* out = (float*)d_out;

    char* scr = nullptr;
    cudaGetSymbolAddress((void**)&scr, g_scratch);
    auto HF = [&](long off) { return (__half*)(scr + off); };

    __half *xs_h = HF(OFF_XS_H);
    __half *xt_h = HF(OFF_XT_H);
    __half *wqt_h = HF(OFF_WQT_H);
    __half *wkt_h = HF(OFF_WKT_H);
    __half *wvt_h = HF(OFF_WVT_H);
    __half *wo_h  = HF(OFF_WO_H);
    __half *P_h = HF(OFF_P_H);
    __half *Q_h = HF(OFF_Q_H);
    __half *G_h = HF(OFF_G_H);
    __half *R_h = HF(OFF_R_H);
    __half *UT_h = HF(OFF_UT_H);

    float* vec = (float*)(scr + OFF_VEC);
    float* s    = vec;                 // [B][E]
    float* p    = s    + Bd * Ed;
    float* r    = p    + Bd * Ed;
    float* u1   = r    + Bd * Ed;
    float* w2   = u1   + Bd * Ed;
    float* t2   = w2   + Bd * Ed;
    float* cb   = t2   + Bd * Ed;
    float* yv   = cb   + Bd * Ed;      // [B][S]
    float* u2   = yv   + Bd * Sd;      // [E]
    float* w1   = u2   + Ed;
    float* t1   = w1   + Ed;
    float* dp   = t1   + Ed;           // [B]
    float* db   = dp   + Bd;           // [1]
    float* part_w  = db + 256;                   // [2][KSW][Ed]
    float* part_mv = part_w + 2 * KSW * Ed;      // [2*Bd][KS][Ed]
    float* part_cs = part_mv + 2 * Bd * KS * Ed; // [Bd][CS][Ed]

    const long sX = (long)Sd * Ed;     // 2M elems
    const long sXT = (long)Ed * Sd;
    const long sEE = (long)Ed * Ed;

    cudaFuncSetAttribute(hf_gemm, cudaFuncAttributeMaxDynamicSharedMemorySize, DYN_SMEM);
    dim3 blk(512);

    // ---- preprocessing (2 launches; x and all W read exactly once) ----
    xsplit_k<<<dim3(Ed / 32, Sd / 32, Bd), dim3(32, 8)>>>(x, sX, xs_h, sX, xt_h, sXT, part_cs);
    tsplitW_k<<<dim3(32, 32, 4), dim3(32, 8)>>>(Wq, Wk, Wv, Wo, bk, bq,
                                                wqt_h, wkt_h, wvt_h, wo_h, part_w);

    // ---- vectors (4 launches) ----
    red1_k<<<dim3(Ed / 64, 6), 256>>>(part_w, part_cs, u2, t1, s);
    rowdot_prw_k<<<dim3(Sd / 8, Bd, 4), 256>>>(Wk, Wv, Wo, x, sX, s, bv, t1, p, r, w1, yv);
    mv2_part_k<<<dim3(Ed / 256, KS, 2 * Bd), 256>>>(Wq, p, x, sX, yv, part_mv);
    red2_k<<<dim3(Ed / 8, Bd, 4), 256>>>(part_mv, Wo, r, p, bk, bq, u1, w2, dp, db, t2);

    // ---- fused GEMM: z<4 -> G_b (tri, K=2048) ; z=4 -> P ; z=5 -> Q ----
    hf_gemm<<<dim3(64, 1, 6), blk, DYN_SMEM>>>(xt_h, sXT, xt_h, sXT,
        nullptr, 0, G_h, sEE, Ed, Sd, 1.f, 0, 1, 1,
        wqt_h, wkt_h, P_h,
        wo_h, wvt_h, Q_h, Ed,
        nullptr, 0, nullptr, nullptr, nullptr, 0, 0.f);
    // cb from Q_h + t2 (single kernel)
    qcb_k<<<dim3(Ed / 8, Bd), 256>>>(Q_h, t2, w1, w2, dp, db, bo, cb);
    mirror_k<<<dim3(Ed / 32, Ed / 32, Bd), dim3(32, 8)>>>(G_h, sEE);

    // R_b = Q G_b (G symmetric -> row-major as B ok)
    hf_gemm<<<dim3(8, 8, Bd), blk, DYN_SMEM>>>(Q_h, 0, G_h, sEE,
        nullptr, 0, R_h, sEE, Ed, Ed, 1.f, 0, 0, 0,
        nullptr, nullptr, nullptr, nullptr, nullptr, nullptr, 0,
        nullptr, 0, nullptr, nullptr, nullptr, 0, 0.f);
    // UT_b = R_b P^T + w2 u2^T + w1 (u1 + S u2)^T
    hf_gemm<<<dim3(8, 8, Bd), blk, DYN_SMEM>>>(R_h, sEE, P_h, 0,
        nullptr, 0, UT_h, sEE, Ed, Ed, 1.f, 1, 0, 0,
        nullptr, nullptr, nullptr, nullptr, nullptr, nullptr, 0,
        w2, Ed, u2, w1, u1, Ed, (float)Sd);
    // out_b = SCALE * x UT^T + c_b
    hf_gemm<<<dim3(8, 16, Bd), blk, DYN_SMEM>>>(xs_h, sX, UT_h, sEE,
        out, sX, nullptr, 0, Ed, Ed, SCALE_F, 2, 0, 0,
        nullptr, nullptr, nullptr, nullptr, nullptr, nullptr, 0,
        cb, Ed, nullptr, nullptr, nullptr, 0, 0.f);
}